// round 2
// baseline (speedup 1.0000x reference)
#include <cuda_runtime.h>
#include <math.h>
#include <stdint.h>

#define Bq  32
#define Bdl 256
#define Bd  768
#define NK  11

__constant__ float c_means[NK] = {-0.9f,-0.7f,-0.5f,-0.3f,-0.1f,0.1f,0.3f,0.5f,0.7f,0.9f,1.0f};

__global__ __launch_bounds__(256, 1)
void knrm_fused(const float* __restrict__ qe,
                const float* __restrict__ de,
                const float* __restrict__ ctx,
                const float* __restrict__ W,
                const float* __restrict__ bias,
                const int*   __restrict__ qlens,
                const int*   __restrict__ dlens,
                float* __restrict__ out)
{
    extern __shared__ float sm[];
    float* Qs   = sm;                       // [32][768]
    float* Bsm  = Qs + Bq*Bd;               // [32][256] k-major, swizzled
    float* dinv = Bsm + 32*Bdl;             // [256]
    float* qinv = dinv + Bdl;               // [32]
    float* soft = qinv + Bq;                // [32][11]
    float* feat = soft + Bq*NK;             // [16]
    float* red  = feat + 16;                // [256]

    const int b     = blockIdx.x;
    const int tid   = threadIdx.x;
    const int qlen1 = qlens[b] + 1;
    const int dlen1 = dlens[b] + 1;

    // zero soft (352 entries -> two strided passes) and feat
    soft[tid]                         = (tid < Bq*NK) ? 0.f : soft[tid]; // tid<256 always < 352
    if (tid + 256 < Bq*NK) soft[tid + 256] = 0.f;
    if (tid < 16)          feat[tid]       = 0.f;

    const float* dgb = de + (size_t)b * Bdl * Bd;
    const int drow = tid >> 3;   // 0..31 : doc row within 32-row group
    const int f4   = tid & 7;    // 0..7  : float4 column chunk within 32-col k-tile

    // ---- prefetch doc K-tile 0 into registers (skip masked doc rows) ----
    float4 pref[8];
    #pragma unroll
    for (int it = 0; it < 8; ++it) {
        int d = it*32 + drow;
        pref[it] = make_float4(0.f,0.f,0.f,0.f);
        if (d < dlen1) pref[it] = *(const float4*)(dgb + (size_t)d*Bd + f4*4);
    }

    // ---- load all queries for this batch into smem (32*768 fl = 6144 float4) ----
    {
        const float4* qg = (const float4*)(qe + (size_t)b * Bq * Bd);
        float4* Q4 = (float4*)Qs;
        #pragma unroll
        for (int it = 0; it < 24; ++it) Q4[it*256 + tid] = qg[it*256 + tid];
    }
    __syncthreads();

    // ---- query inverse norms (8 threads per query row) ----
    {
        int q = tid >> 3, c = tid & 7;
        const float4* row = (const float4*)(Qs + q*Bd);
        float s = 0.f;
        #pragma unroll
        for (int j = 0; j < 24; ++j) {
            float4 v = row[c + 8*j];
            s += v.x*v.x + v.y*v.y + v.z*v.z + v.w*v.w;
        }
        s += __shfl_xor_sync(0xffffffffu, s, 4);
        s += __shfl_xor_sync(0xffffffffu, s, 2);
        s += __shfl_xor_sync(0xffffffffu, s, 1);
        if (c == 0) qinv[q] = rsqrtf(s);
    }

    // GEMM thread tile: 8 query rows x 4 docs
    const int qb = (tid >> 6) * 8;            // 0,8,16,24
    const int db = (tid & 63) * 4;            // 0..252
    const bool warp_active = ((((tid >> 5) & 1) * 128) < dlen1); // warp-uniform doc-half skip

    float acc[8][4];
    #pragma unroll
    for (int i = 0; i < 8; ++i)
        #pragma unroll
        for (int j = 0; j < 4; ++j) acc[i][j] = 0.f;
    float dn[8];
    #pragma unroll
    for (int i = 0; i < 8; ++i) dn[i] = 0.f;

    // ---- main K loop: 24 tiles of 32 ----
    for (int kt = 0; kt < 24; ++kt) {
        __syncthreads();
        // store prefetched tile into swizzled k-major smem; fuse doc-norm accum
        #pragma unroll
        for (int it = 0; it < 8; ++it) {
            int d = it*32 + drow;
            float4 v = pref[it];
            dn[it] += v.x*v.x + v.y*v.y + v.z*v.z + v.w*v.w;
            int col = d ^ (f4 << 2);                  // XOR swizzle: conflict-free STS & LDS
            Bsm[(f4*4+0)*Bdl + col] = v.x;
            Bsm[(f4*4+1)*Bdl + col] = v.y;
            Bsm[(f4*4+2)*Bdl + col] = v.z;
            Bsm[(f4*4+3)*Bdl + col] = v.w;
        }
        __syncthreads();
        // prefetch next tile (hidden under compute below)
        if (kt < 23) {
            const float* src = dgb + (size_t)(kt+1)*32 + f4*4;
            #pragma unroll
            for (int it = 0; it < 8; ++it) {
                int d = it*32 + drow;
                if (d < dlen1) pref[it] = *(const float4*)(src + (size_t)d*Bd);
                else           pref[it] = make_float4(0.f,0.f,0.f,0.f);
            }
        }
        // compute: 32q x 256d x 32k per CTA-tile
        if (warp_active) {
            #pragma unroll
            for (int kk4 = 0; kk4 < 8; ++kk4) {
                float4 av[8];
                #pragma unroll
                for (int i = 0; i < 8; ++i)
                    av[i] = *(const float4*)(Qs + (qb+i)*Bd + kt*32 + kk4*4); // warp broadcast
                int colb = db ^ (kk4 << 2);
                #pragma unroll
                for (int j = 0; j < 4; ++j) {
                    float4 bv = *(const float4*)(Bsm + (kk4*4 + j)*Bdl + colb);
                    #pragma unroll
                    for (int i = 0; i < 8; ++i) {
                        float a = (&av[i].x)[j];
                        acc[i][0] = fmaf(a, bv.x, acc[i][0]);
                        acc[i][1] = fmaf(a, bv.y, acc[i][1]);
                        acc[i][2] = fmaf(a, bv.z, acc[i][2]);
                        acc[i][3] = fmaf(a, bv.w, acc[i][3]);
                    }
                }
            }
        }
    }

    // ---- doc inverse norms (reduce 8 f4-lanes per doc) ----
    #pragma unroll
    for (int it = 0; it < 8; ++it) {
        float s = dn[it];
        s += __shfl_xor_sync(0xffffffffu, s, 4);
        s += __shfl_xor_sync(0xffffffffu, s, 2);
        s += __shfl_xor_sync(0xffffffffu, s, 1);
        if (f4 == 0) dinv[it*32 + drow] = rsqrtf(s);
    }
    __syncthreads();

    // ---- RBF kernel pooling over unmasked pairs only ----
    #pragma unroll 1
    for (int iq = 0; iq < 8; ++iq) {
        int q = qb + iq;
        if (q >= qlen1) continue;          // warp-uniform
        float ka[NK];
        #pragma unroll
        for (int k = 0; k < NK; ++k) ka[k] = 0.f;
        float qi = qinv[q];
        #pragma unroll
        for (int j = 0; j < 4; ++j) {
            int d = db + j;
            if (d < dlen1) {
                float s = acc[iq][j] * qi * dinv[d];
                #pragma unroll
                for (int k = 0; k < NK; ++k) {
                    float diff = s - c_means[k];
                    float iv = (k < 10) ? 50.0f : 500000.0f;
                    ka[k] += expf(-diff*diff*iv);
                }
            }
        }
        #pragma unroll
        for (int k = 0; k < NK; ++k) {
            float v = ka[k];
            v += __shfl_xor_sync(0xffffffffu, v, 16);
            v += __shfl_xor_sync(0xffffffffu, v, 8);
            v += __shfl_xor_sync(0xffffffffu, v, 4);
            v += __shfl_xor_sync(0xffffffffu, v, 2);
            v += __shfl_xor_sync(0xffffffffu, v, 1);
            if ((tid & 31) == 0) atomicAdd(&soft[q*NK + k], v);
        }
    }
    __syncthreads();

    // ---- add analytic masked contributions, take log, sum over q ----
    if (tid < Bq) {
        int q = tid;
        #pragma unroll
        for (int k = 0; k < NK; ++k) {
            float m  = c_means[k];
            float iv = (k < 10) ? 50.0f : 500000.0f;
            float ck = expf(-m*m*iv);
            float v = (q < qlen1) ? (soft[q*NK+k] + (float)(Bdl - dlen1)*ck)
                                  : ((float)Bdl * ck);
            atomicAdd(&feat[k], logf(v));   // log(0) -> -inf matches reference
        }
    }
    __syncthreads();

    // ---- final linear layer + tanh ----
    {
        const float* cb = ctx + (size_t)b*Bd;
        float part = cb[tid]       * W[NK + tid]
                   + cb[tid + 256] * W[NK + tid + 256]
                   + cb[tid + 512] * W[NK + tid + 512];
        if (tid < NK) part += feat[tid] * W[tid];
        red[tid] = part;
        __syncthreads();
        #pragma unroll
        for (int s = 128; s > 0; s >>= 1) {
            if (tid < s) red[tid] += red[tid + s];
            __syncthreads();
        }
        if (tid == 0) out[b] = tanhf(red[0] + bias[0]);
    }
}

extern "C" void kernel_launch(void* const* d_in, const int* in_sizes, int n_in,
                              void* d_out, int out_size)
{
    const float* qe = (const float*)d_in[0];
    const float* de = (const float*)d_in[1];
    const float* cv = (const float*)d_in[2];
    const float* W  = (const float*)d_in[3];
    const float* bb = (const float*)d_in[4];
    const int*   ql = (const int*)d_in[5];
    const int*   dl = (const int*)d_in[6];
    float* out = (float*)d_out;

    int smem = (Bq*Bd + 32*Bdl + Bdl + Bq + Bq*NK + 16 + 256) * (int)sizeof(float);
    cudaFuncSetAttribute(knrm_fused, cudaFuncAttributeMaxDynamicSharedMemorySize, smem);
    knrm_fused<<<256, 256, smem>>>(qe, de, cv, W, bb, ql, dl, out);
}

// round 4
// speedup vs baseline: 1.2642x; 1.2642x over previous
#include <cuda_runtime.h>
#include <math.h>
#include <stdint.h>

#define Bq  32
#define Bdl 256
#define Bd  768
#define NK  11

__constant__ float c_means[NK] = {-0.9f,-0.7f,-0.5f,-0.3f,-0.1f,0.1f,0.3f,0.5f,0.7f,0.9f,1.0f};

__global__ __launch_bounds__(256, 2)
void knrm_fused(const float* __restrict__ qe,
                const float* __restrict__ de,
                const float* __restrict__ ctx,
                const float* __restrict__ W,
                const float* __restrict__ bias,
                const int*   __restrict__ qlens,
                const int*   __restrict__ dlens,
                float* __restrict__ out)
{
    extern __shared__ float sm[];
    float* As   = sm;                       // [2][32][32]   A tiles (q-major)
    float* Bs   = As + 2*Bq*32;             // [2][32][256]  B tiles (k-major, swizzled)
    float* dinv = Bs + 2*32*Bdl;            // [256]
    float* qinv = dinv + Bdl;               // [32]
    float* soft = qinv + Bq;                // [32][11]
    float* feat = soft + Bq*NK;             // [16]
    float* red  = feat + 16;                // [256]

    const int b     = blockIdx.x;
    const int tid   = threadIdx.x;
    const int qlen1 = qlens[b] + 1;
    const int dlen1 = dlens[b] + 1;

    // zero soft (352 entries) and feat
    if (tid < Bq*NK)       soft[tid]       = 0.f;
    if (tid + 256 < Bq*NK) soft[tid + 256] = 0.f;
    if (tid < 16)          feat[tid]       = 0.f;

    const float* dgb = de + (size_t)b * Bdl * Bd;
    const float* qgb = qe + (size_t)b * Bq  * Bd;
    const int drow = tid >> 3;   // 0..31 : doc row within 32-row group (B load role)
    const int f4   = tid & 7;    // 0..7  : float4 k-chunk within 32-col k-tile
    const int qrow = tid >> 3;   // 0..31 : query row (A load role, same decomposition)

    // ---- prefetch B K-tile 0 into registers (skip masked doc rows) ----
    float4 pref[8];
    #pragma unroll
    for (int it = 0; it < 8; ++it) {
        int d = it*32 + drow;
        pref[it] = make_float4(0.f,0.f,0.f,0.f);
        if (d < dlen1) pref[it] = *(const float4*)(dgb + (size_t)d*Bd + f4*4);
    }
    // ---- prefetch A K-tile 0 (one float4 per thread) ----
    float4 a4 = *(const float4*)(qgb + (size_t)qrow*Bd + f4*4);

    // store A tile 0 into As[0]; start q-norm accumulation
    *(float4*)(As + qrow*32 + f4*4) = a4;
    float qn = a4.x*a4.x + a4.y*a4.y + a4.z*a4.z + a4.w*a4.w;

    // GEMM thread tile: 8 query rows x 4 docs
    const int qb = (tid >> 6) * 8;            // 0,8,16,24
    const int db = (tid & 63) * 4;            // 0..252
    const bool warp_active = ((((tid >> 5) & 1) * 128) < dlen1); // warp-uniform doc-half skip

    float acc[8][4];
    #pragma unroll
    for (int i = 0; i < 8; ++i)
        #pragma unroll
        for (int j = 0; j < 4; ++j) acc[i][j] = 0.f;
    float dn[8];
    #pragma unroll
    for (int i = 0; i < 8; ++i) dn[i] = 0.f;

    // ---- main K loop: 24 tiles of 32, double-buffered, one sync per tile ----
    for (int kt = 0; kt < 24; ++kt) {
        const int p = kt & 1;
        // commit prefetched B tile into swizzled k-major smem; fuse doc-norm accum
        float* Bw = Bs + p*8192;
        #pragma unroll
        for (int it = 0; it < 8; ++it) {
            int d = it*32 + drow;
            float4 v = pref[it];
            dn[it] += v.x*v.x + v.y*v.y + v.z*v.z + v.w*v.w;
            int col = d ^ (f4 << 2);                  // XOR swizzle: conflict-free STS & LDS
            Bw[(f4*4+0)*Bdl + col] = v.x;
            Bw[(f4*4+1)*Bdl + col] = v.y;
            Bw[(f4*4+2)*Bdl + col] = v.z;
            Bw[(f4*4+3)*Bdl + col] = v.w;
        }
        // prefetch next tiles (global latency hidden under sync + compute)
        if (kt < 23) {
            const float* src = dgb + (size_t)(kt+1)*32 + f4*4;
            #pragma unroll
            for (int it = 0; it < 8; ++it) {
                int d = it*32 + drow;
                if (d < dlen1) pref[it] = *(const float4*)(src + (size_t)d*Bd);
                else           pref[it] = make_float4(0.f,0.f,0.f,0.f);
            }
            a4 = *(const float4*)(qgb + (size_t)qrow*Bd + (kt+1)*32 + f4*4);
        }
        __syncthreads();
        // stage next A tile into the alternate buffer (consumed after next sync)
        if (kt < 23) {
            *(float4*)(As + (p^1)*1024 + qrow*32 + f4*4) = a4;
            qn += a4.x*a4.x + a4.y*a4.y + a4.z*a4.z + a4.w*a4.w;
        }
        // compute: 32q x 256d x 32k per CTA-tile
        if (warp_active) {
            const float* Ap = As + p*1024 + qb*32;
            const float* Bp = Bs + p*8192;
            #pragma unroll
            for (int kk4 = 0; kk4 < 8; ++kk4) {
                int colb = db ^ (kk4 << 2);
                float4 bv0 = *(const float4*)(Bp + (kk4*4+0)*Bdl + colb);
                float4 bv1 = *(const float4*)(Bp + (kk4*4+1)*Bdl + colb);
                float4 bv2 = *(const float4*)(Bp + (kk4*4+2)*Bdl + colb);
                float4 bv3 = *(const float4*)(Bp + (kk4*4+3)*Bdl + colb);
                #pragma unroll
                for (int i = 0; i < 8; ++i) {
                    float4 av = *(const float4*)(Ap + i*32 + kk4*4);   // warp broadcast
                    acc[i][0] = fmaf(av.x, bv0.x, acc[i][0]);
                    acc[i][1] = fmaf(av.x, bv0.y, acc[i][1]);
                    acc[i][2] = fmaf(av.x, bv0.z, acc[i][2]);
                    acc[i][3] = fmaf(av.x, bv0.w, acc[i][3]);
                    acc[i][0] = fmaf(av.y, bv1.x, acc[i][0]);
                    acc[i][1] = fmaf(av.y, bv1.y, acc[i][1]);
                    acc[i][2] = fmaf(av.y, bv1.z, acc[i][2]);
                    acc[i][3] = fmaf(av.y, bv1.w, acc[i][3]);
                    acc[i][0] = fmaf(av.z, bv2.x, acc[i][0]);
                    acc[i][1] = fmaf(av.z, bv2.y, acc[i][1]);
                    acc[i][2] = fmaf(av.z, bv2.z, acc[i][2]);
                    acc[i][3] = fmaf(av.z, bv2.w, acc[i][3]);
                    acc[i][0] = fmaf(av.w, bv3.x, acc[i][0]);
                    acc[i][1] = fmaf(av.w, bv3.y, acc[i][1]);
                    acc[i][2] = fmaf(av.w, bv3.z, acc[i][2]);
                    acc[i][3] = fmaf(av.w, bv3.w, acc[i][3]);
                }
            }
        }
    }

    // ---- query inverse norms (8 lanes per q share one warp) ----
    qn += __shfl_xor_sync(0xffffffffu, qn, 4);
    qn += __shfl_xor_sync(0xffffffffu, qn, 2);
    qn += __shfl_xor_sync(0xffffffffu, qn, 1);
    if (f4 == 0) qinv[qrow] = rsqrtf(qn);

    // ---- doc inverse norms (reduce 8 f4-lanes per doc) ----
    #pragma unroll
    for (int it = 0; it < 8; ++it) {
        float s = dn[it];
        s += __shfl_xor_sync(0xffffffffu, s, 4);
        s += __shfl_xor_sync(0xffffffffu, s, 2);
        s += __shfl_xor_sync(0xffffffffu, s, 1);
        if (f4 == 0) dinv[it*32 + drow] = rsqrtf(s);
    }
    __syncthreads();

    // ---- RBF kernel pooling over unmasked pairs only ----
    #pragma unroll 1
    for (int iq = 0; iq < 8; ++iq) {
        int q = qb + iq;
        if (q >= qlen1) continue;          // warp-uniform
        float ka[NK];
        #pragma unroll
        for (int k = 0; k < NK; ++k) ka[k] = 0.f;
        float qi = qinv[q];
        #pragma unroll
        for (int j = 0; j < 4; ++j) {
            int d = db + j;
            if (d < dlen1) {
                float s = acc[iq][j] * qi * dinv[d];
                #pragma unroll
                for (int k = 0; k < NK; ++k) {
                    float diff = s - c_means[k];
                    float iv = (k < 10) ? 50.0f : 500000.0f;
                    ka[k] += expf(-diff*diff*iv);
                }
            }
        }
        #pragma unroll
        for (int k = 0; k < NK; ++k) {
            float v = ka[k];
            v += __shfl_xor_sync(0xffffffffu, v, 16);
            v += __shfl_xor_sync(0xffffffffu, v, 8);
            v += __shfl_xor_sync(0xffffffffu, v, 4);
            v += __shfl_xor_sync(0xffffffffu, v, 2);
            v += __shfl_xor_sync(0xffffffffu, v, 1);
            if ((tid & 31) == 0) atomicAdd(&soft[q*NK + k], v);
        }
    }
    __syncthreads();

    // ---- add analytic masked contributions, take log, sum over q ----
    if (tid < Bq) {
        int q = tid;
        #pragma unroll
        for (int k = 0; k < NK; ++k) {
            float m  = c_means[k];
            float iv = (k < 10) ? 50.0f : 500000.0f;
            float ck = expf(-m*m*iv);
            float v = (q < qlen1) ? (soft[q*NK+k] + (float)(Bdl - dlen1)*ck)
                                  : ((float)Bdl * ck);
            atomicAdd(&feat[k], logf(v));   // log(0) -> -inf matches reference
        }
    }
    __syncthreads();

    // ---- final linear layer + tanh ----
    {
        const float* cb = ctx + (size_t)b*Bd;
        float part = cb[tid]       * W[NK + tid]
                   + cb[tid + 256] * W[NK + tid + 256]
                   + cb[tid + 512] * W[NK + tid + 512];
        if (tid < NK) part += feat[tid] * W[tid];
        red[tid] = part;
        __syncthreads();
        #pragma unroll
        for (int s = 128; s > 0; s >>= 1) {
            if (tid < s) red[tid] += red[tid + s];
            __syncthreads();
        }
        if (tid == 0) out[b] = tanhf(red[0] + bias[0]);
    }
}

extern "C" void kernel_launch(void* const* d_in, const int* in_sizes, int n_in,
                              void* d_out, int out_size)
{
    const float* qe = (const float*)d_in[0];
    const float* de = (const float*)d_in[1];
    const float* cv = (const float*)d_in[2];
    const float* W  = (const float*)d_in[3];
    const float* bb = (const float*)d_in[4];
    const int*   ql = (const int*)d_in[5];
    const int*   dl = (const int*)d_in[6];
    float* out = (float*)d_out;

    int smem = (2*Bq*32 + 2*32*Bdl + Bdl + Bq + Bq*NK + 16 + 256) * (int)sizeof(float);
    cudaFuncSetAttribute(knrm_fused, cudaFuncAttributeMaxDynamicSharedMemorySize, smem);
    knrm_fused<<<256, 256, smem>>>(qe, de, cv, W, bb, ql, dl, out);
}